// round 1
// baseline (speedup 1.0000x reference)
#include <cuda_runtime.h>
#include <cstring>

// Problem (fixed by dataset): B=4, N=2048, Fin=128, H=4, Fout=32.
// Key identity: softmax(scores, axis=m).sum(axis=m) == 1, so the reference
// reduces to out = (1 + self_weight) * (x @ W). adj and att are dead inputs.
//
// This kernel: fp32 SGEMM  [M=8192, K=128] @ [K=128, N=128], epilogue scale.
// Uses packed fma.rn.f32x2 (FFMA2) for 2x fp32 FMA throughput on sm_103a.

#define KDIM 128
#define NDIM 128
#define TM 64      // rows per block
#define TN 64      // cols per block
#define KB 32      // K chunk staged in smem

__device__ __forceinline__ void fma2(unsigned long long& d,
                                     unsigned long long a,
                                     unsigned long long b) {
    asm("fma.rn.f32x2 %0, %1, %2, %0;" : "+l"(d) : "l"(a), "l"(b));
}

__device__ __forceinline__ unsigned long long dup2(float x) {
    unsigned long long r;
    asm("mov.b64 %0, {%1, %1};" : "=l"(r) : "f"(x));
    return r;
}

__global__ __launch_bounds__(256, 2)
void gat_gemm_kernel(const float* __restrict__ x,
                     const float* __restrict__ W,
                     const float* __restrict__ self_weight,
                     float* __restrict__ out) {
    __shared__ float xs[TM][KB];   // 8 KB: x tile  [64 rows][32 k]
    __shared__ float ws[KB][TN];   // 8 KB: W tile  [32 k][64 cols]

    const int tid  = threadIdx.x;
    const int bcol = blockIdx.x & 1;        // 2 column tiles (128/64)
    const int brow = blockIdx.x >> 1;       // 128 row tiles  (8192/64)
    const int row0 = brow * TM;
    const int col0 = bcol * TN;

    // thread -> 4 rows x 4 cols of the 64x64 tile
    const int cx = tid & 15;                // col quad: cols cx*4 .. cx*4+3
    const int ry = tid >> 4;                // row quad: rows ry*4 .. ry*4+3

    unsigned long long acc[4][2];
    #pragma unroll
    for (int i = 0; i < 4; i++) { acc[i][0] = 0ull; acc[i][1] = 0ull; }

    #pragma unroll
    for (int kb = 0; kb < KDIM; kb += KB) {
        // ---- stage x tile and W tile (512 float4 each half... 512 total per buf) ----
        {
            // xs: 64 rows x 32 floats = 512 float4 ; ws: 32 rows x 64 floats = 512 float4
            int s0 = tid;          // slots tid and tid+256
            #pragma unroll
            for (int rep = 0; rep < 2; rep++) {
                int s = s0 + rep * 256;
                int xr = s >> 3, xq = s & 7;    // xs[xr][xq*4]
                ((float4*)xs)[s] =
                    *(const float4*)&x[(size_t)(row0 + xr) * KDIM + kb + xq * 4];
                int wr = s >> 4, wq = s & 15;   // ws[wr][wq*4]
                ((float4*)ws)[s] =
                    *(const float4*)&W[(size_t)(kb + wr) * NDIM + col0 + wq * 4];
            }
        }
        __syncthreads();

        // ---- compute: 32 k-steps, unrolled by 4 ----
        #pragma unroll
        for (int k4 = 0; k4 < KB; k4 += 4) {
            float4 xq[4];
            #pragma unroll
            for (int i = 0; i < 4; i++)
                xq[i] = *(const float4*)&xs[ry * 4 + i][k4];

            #pragma unroll
            for (int kk = 0; kk < 4; kk++) {
                // W row as two packed f32x2 (lo,hi pairing matches float order)
                ulonglong2 w2 = *(const ulonglong2*)&ws[k4 + kk][cx * 4];
                #pragma unroll
                for (int i = 0; i < 4; i++) {
                    float xv = (kk == 0) ? xq[i].x :
                               (kk == 1) ? xq[i].y :
                               (kk == 2) ? xq[i].z : xq[i].w;
                    unsigned long long x2 = dup2(xv);
                    fma2(acc[i][0], x2, w2.x);
                    fma2(acc[i][1], x2, w2.y);
                }
            }
        }
        __syncthreads();
    }

    // ---- epilogue: scale by (1 + self_weight) and store ----
    const float scale = 1.0f + self_weight[0];
    #pragma unroll
    for (int i = 0; i < 4; i++) {
        float2 a0, a1;
        memcpy(&a0, &acc[i][0], 8);
        memcpy(&a1, &acc[i][1], 8);
        float4 o;
        o.x = a0.x * scale; o.y = a0.y * scale;
        o.z = a1.x * scale; o.w = a1.y * scale;
        *(float4*)&out[(size_t)(row0 + ry * 4 + i) * NDIM + col0 + cx * 4] = o;
    }
}

extern "C" void kernel_launch(void* const* d_in, const int* in_sizes, int n_in,
                              void* d_out, int out_size) {
    // metadata order: x (f32), adj (i32, UNUSED), W (f32), att (f32, UNUSED),
    //                 self_weight (f32)
    const float* x  = (const float*)d_in[0];
    const float* W  = (const float*)d_in[2];
    const float* sw = (const float*)d_in[4];
    float* out      = (float*)d_out;

    const int M = in_sizes[0] / KDIM;          // 8192
    dim3 grid((M / TM) * (NDIM / TN));         // 128 * 2 = 256 blocks
    gat_gemm_kernel<<<grid, 256>>>(x, W, sw, out);
}